// round 2
// baseline (speedup 1.0000x reference)
#include <cuda_runtime.h>
#include <math.h>

#define N_NODES 100000
#define N_EDGES 1600000
#define N_FEATS 9
#define HID 64
#define HID2 128
#define NG 512
#define EPS_MSG 1e-7f
#define BN_EPS 1e-5f

// ---------------- scratch (static device globals; no runtime alloc) ----------
__device__ int   g_sorted_src[N_EDGES];
__device__ int   g_deg[N_NODES];
__device__ int   g_rowptr[N_NODES + 1];
__device__ int   g_cursor[N_NODES];
__device__ float g_xsrc[N_NODES * HID];
__device__ float g_xdst[N_NODES * HID];
__device__ float g_y[N_NODES * HID];
__device__ float g_z[(size_t)N_NODES * HID2];
__device__ float g_h[N_NODES * HID];
__device__ float g_bnsum[HID2];
__device__ float g_bnsq[HID2];
__device__ float g_scale[HID2];
__device__ float g_shift[HID2];
__device__ float g_pool[NG * HID];
__device__ float g_cnt[NG];

// ---------------- CSR build ------------------------------------------------
// edge_index is int32 (JAX x64 disabled coerces int64 -> int32)
__global__ void k_hist(const int* __restrict__ ei, int E) {
    int e = blockIdx.x * blockDim.x + threadIdx.x;
    if (e >= E) return;
    int d = ei[E + e];
    atomicAdd(&g_deg[d], 1);
}

__global__ void k_scan(int n) {
    __shared__ int part[1024];
    int tid = threadIdx.x;
    int chunk = (n + 1023) >> 10;
    int start = tid * chunk;
    int end = min(start + chunk, n);
    int s = 0;
    for (int i = start; i < end; i++) s += g_deg[i];
    part[tid] = s;
    __syncthreads();
    // Hillis-Steele inclusive scan
    for (int d = 1; d < 1024; d <<= 1) {
        int v = part[tid];
        int a = (tid >= d) ? part[tid - d] : 0;
        __syncthreads();
        part[tid] = v + a;
        __syncthreads();
    }
    int off = part[tid] - s;  // exclusive prefix
    for (int i = start; i < end; i++) {
        g_rowptr[i] = off;
        g_cursor[i] = off;
        off += g_deg[i];
    }
    if (tid == 1023) g_rowptr[n] = part[1023];
}

__global__ void k_scatter(const int* __restrict__ ei, int E) {
    int e = blockIdx.x * blockDim.x + threadIdx.x;
    if (e >= E) return;
    int s = ei[e];
    int d = ei[E + e];
    int p = atomicAdd(&g_cursor[d], 1);
    g_sorted_src[p] = s;
}

// ---------------- input projection: x@w_src+b_src, x@w_dst+b_dst -----------
__global__ void k_inproj(const float* __restrict__ x,
                         const float* __restrict__ wsrc, const float* __restrict__ bsrc,
                         const float* __restrict__ wdst, const float* __restrict__ bdst,
                         int n) {
    int idx = blockIdx.x * blockDim.x + threadIdx.x;
    if (idx >= n * HID) return;
    int node = idx >> 6;
    int c = idx & 63;
    const float* xr = x + (size_t)node * N_FEATS;
    float a = bsrc[c], b = bdst[c];
#pragma unroll
    for (int k = 0; k < N_FEATS; k++) {
        float xv = xr[k];
        a += xv * wsrc[k * HID + c];
        b += xv * wdst[k * HID + c];
    }
    g_xsrc[idx] = a;
    g_xdst[idx] = b;
}

// ---------------- softmax aggregation: warp per dst node -------------------
// aggr[n][c] = sum_e exp(m)*m / (sum_e exp(m)), m = relu(fsrc[src][c]) + eps
// (softmax is shift-invariant; activations are O(1) so no max-subtraction)
__global__ void k_aggr(const float* __restrict__ fsrc,
                       const float* __restrict__ fdst,
                       float* __restrict__ y, int n) {
    int warp = (blockIdx.x * blockDim.x + threadIdx.x) >> 5;
    int lane = threadIdx.x & 31;
    if (warp >= n) return;
    int beg = g_rowptr[warp], end = g_rowptr[warp + 1];
    int c = lane * 2;
    float s0 = 0.f, s1 = 0.f, t0 = 0.f, t1 = 0.f;
    for (int i = beg; i < end; i++) {
        int src = g_sorted_src[i];
        float2 v = *(const float2*)(fsrc + (size_t)src * HID + c);
        float v0 = fmaxf(v.x, 0.f) + EPS_MSG;
        float v1 = fmaxf(v.y, 0.f) + EPS_MSG;
        float e0 = __expf(v0);
        float e1 = __expf(v1);
        s0 += e0; t0 += e0 * v0;
        s1 += e1; t1 += e1 * v1;
    }
    float2 dv = *(const float2*)(fdst + (size_t)warp * HID + c);
    float2 o;
    o.x = t0 / (s0 + 1e-16f) + dv.x;
    o.y = t1 / (s1 + 1e-16f) + dv.y;
    *(float2*)(y + (size_t)warp * HID + c) = o;
}

// ---------------- GEMM1: z = y[64] @ w1[64x128] + b1 -----------------------
__global__ void k_gemm1(const float* __restrict__ y,
                        const float* __restrict__ w1, const float* __restrict__ b1,
                        float* __restrict__ z, int n) {
    __shared__ float ys[64][HID];    // 16 KB
    __shared__ float ws[HID][HID2];  // 32 KB
    int t = threadIdx.x;             // 256
    int row0 = blockIdx.x * 64;

    for (int i = t * 4; i < HID * HID2; i += 1024)
        *(float4*)((float*)ws + i) = *(const float4*)(w1 + i);
    for (int i = t * 4; i < 64 * HID; i += 1024) {
        int r = i >> 6, cc = i & 63;
        float4 v = make_float4(0.f, 0.f, 0.f, 0.f);
        if (row0 + r < n) v = *(const float4*)(y + (size_t)(row0 + r) * HID + cc);
        *(float4*)(&ys[r][cc]) = v;
    }
    __syncthreads();

    int r0 = (t >> 4) * 4;   // 0..60
    int c0 = (t & 15) * 8;   // 0..120
    float acc[4][8];
#pragma unroll
    for (int i = 0; i < 4; i++)
#pragma unroll
        for (int j = 0; j < 8; j++) acc[i][j] = 0.f;

#pragma unroll 8
    for (int k = 0; k < HID; k++) {
        float a0 = ys[r0][k], a1 = ys[r0 + 1][k], a2 = ys[r0 + 2][k], a3 = ys[r0 + 3][k];
        float4 bA = *(float4*)(&ws[k][c0]);
        float4 bB = *(float4*)(&ws[k][c0 + 4]);
        acc[0][0] += a0 * bA.x; acc[0][1] += a0 * bA.y; acc[0][2] += a0 * bA.z; acc[0][3] += a0 * bA.w;
        acc[0][4] += a0 * bB.x; acc[0][5] += a0 * bB.y; acc[0][6] += a0 * bB.z; acc[0][7] += a0 * bB.w;
        acc[1][0] += a1 * bA.x; acc[1][1] += a1 * bA.y; acc[1][2] += a1 * bA.z; acc[1][3] += a1 * bA.w;
        acc[1][4] += a1 * bB.x; acc[1][5] += a1 * bB.y; acc[1][6] += a1 * bB.z; acc[1][7] += a1 * bB.w;
        acc[2][0] += a2 * bA.x; acc[2][1] += a2 * bA.y; acc[2][2] += a2 * bA.z; acc[2][3] += a2 * bA.w;
        acc[2][4] += a2 * bB.x; acc[2][5] += a2 * bB.y; acc[2][6] += a2 * bB.z; acc[2][7] += a2 * bB.w;
        acc[3][0] += a3 * bA.x; acc[3][1] += a3 * bA.y; acc[3][2] += a3 * bA.z; acc[3][3] += a3 * bA.w;
        acc[3][4] += a3 * bB.x; acc[3][5] += a3 * bB.y; acc[3][6] += a3 * bB.z; acc[3][7] += a3 * bB.w;
    }

    float4 b1A = *(const float4*)(b1 + c0);
    float4 b1B = *(const float4*)(b1 + c0 + 4);
#pragma unroll
    for (int i = 0; i < 4; i++) {
        int r = row0 + r0 + i;
        if (r < n) {
            float4 oA, oB;
            oA.x = acc[i][0] + b1A.x; oA.y = acc[i][1] + b1A.y;
            oA.z = acc[i][2] + b1A.z; oA.w = acc[i][3] + b1A.w;
            oB.x = acc[i][4] + b1B.x; oB.y = acc[i][5] + b1B.y;
            oB.z = acc[i][6] + b1B.z; oB.w = acc[i][7] + b1B.w;
            *(float4*)(z + (size_t)r * HID2 + c0) = oA;
            *(float4*)(z + (size_t)r * HID2 + c0 + 4) = oB;
        }
    }
}

// ---------------- BN stats / finalize ---------------------------------------
__global__ void k_stats(const float* __restrict__ z, int n) {
    int c = threadIdx.x;  // 128
    float s = 0.f, q = 0.f;
    for (int r = blockIdx.x; r < n; r += gridDim.x) {
        float v = z[(size_t)r * HID2 + c];
        s += v;
        q += v * v;
    }
    atomicAdd(&g_bnsum[c], s);
    atomicAdd(&g_bnsq[c], q);
}

__global__ void k_bnfin(const float* __restrict__ gma, const float* __restrict__ bet, float inv_n) {
    int c = threadIdx.x;
    float mu = g_bnsum[c] * inv_n;
    float var = g_bnsq[c] * inv_n - mu * mu;
    float sc = gma[c] * rsqrtf(var + BN_EPS);
    g_scale[c] = sc;
    g_shift[c] = bet[c] - mu * sc;
}

// ---------------- GEMM2: h = relu( relu(BN(z)) @ w2[128x64] + b2 ) ----------
__global__ void k_gemm2(const float* __restrict__ z,
                        const float* __restrict__ w2, const float* __restrict__ b2,
                        float* __restrict__ h, int n) {
    __shared__ float zs[64][65];   // padded
    __shared__ float ws[64][HID];  // k-slice of w2
    int t = threadIdx.x;           // 256
    int row0 = blockIdx.x * 64;
    int r0 = (t >> 4) * 4;
    int c0 = (t & 15) * 4;
    float acc[4][4];
#pragma unroll
    for (int i = 0; i < 4; i++)
#pragma unroll
        for (int j = 0; j < 4; j++) acc[i][j] = 0.f;

    for (int k0 = 0; k0 < HID2; k0 += 64) {
        __syncthreads();
        for (int i = t * 4; i < 64 * 64; i += 1024) {
            int r = i >> 6, kk = i & 63;
            float4 v = make_float4(0.f, 0.f, 0.f, 0.f);
            if (row0 + r < n) v = *(const float4*)(z + (size_t)(row0 + r) * HID2 + k0 + kk);
            float4 sc = *(const float4*)(&g_scale[k0 + kk]);
            float4 sh = *(const float4*)(&g_shift[k0 + kk]);
            zs[r][kk]     = fmaxf(v.x * sc.x + sh.x, 0.f);
            zs[r][kk + 1] = fmaxf(v.y * sc.y + sh.y, 0.f);
            zs[r][kk + 2] = fmaxf(v.z * sc.z + sh.z, 0.f);
            zs[r][kk + 3] = fmaxf(v.w * sc.w + sh.w, 0.f);
        }
        for (int i = t * 4; i < 64 * HID; i += 1024)
            *(float4*)((float*)ws + i) = *(const float4*)(w2 + (size_t)k0 * HID + i);
        __syncthreads();

#pragma unroll 8
        for (int k = 0; k < 64; k++) {
            float a0 = zs[r0][k], a1 = zs[r0 + 1][k], a2 = zs[r0 + 2][k], a3 = zs[r0 + 3][k];
            float4 b = *(float4*)(&ws[k][c0]);
            acc[0][0] += a0 * b.x; acc[0][1] += a0 * b.y; acc[0][2] += a0 * b.z; acc[0][3] += a0 * b.w;
            acc[1][0] += a1 * b.x; acc[1][1] += a1 * b.y; acc[1][2] += a1 * b.z; acc[1][3] += a1 * b.w;
            acc[2][0] += a2 * b.x; acc[2][1] += a2 * b.y; acc[2][2] += a2 * b.z; acc[2][3] += a2 * b.w;
            acc[3][0] += a3 * b.x; acc[3][1] += a3 * b.y; acc[3][2] += a3 * b.z; acc[3][3] += a3 * b.w;
        }
    }

    float4 bb = *(const float4*)(b2 + c0);
#pragma unroll
    for (int i = 0; i < 4; i++) {
        int r = row0 + r0 + i;
        if (r < n) {
            float4 o;
            o.x = fmaxf(acc[i][0] + bb.x, 0.f);
            o.y = fmaxf(acc[i][1] + bb.y, 0.f);
            o.z = fmaxf(acc[i][2] + bb.z, 0.f);
            o.w = fmaxf(acc[i][3] + bb.w, 0.f);
            *(float4*)(h + (size_t)r * HID + c0) = o;
        }
    }
}

// ---------------- pooling + head --------------------------------------------
__global__ void k_pool(const int* __restrict__ bidx, int n) {
    int idx = blockIdx.x * blockDim.x + threadIdx.x;
    if (idx >= n * 32) return;
    int node = idx >> 5;
    int c2 = (idx & 31) * 2;
    int g = bidx[node];
    float2 v = *(const float2*)(g_h + (size_t)node * HID + c2);
    atomicAdd(&g_pool[g * HID + c2], v.x);
    atomicAdd(&g_pool[g * HID + c2 + 1], v.y);
}

__global__ void k_cnt(const int* __restrict__ bidx, int n) {
    int i = blockIdx.x * blockDim.x + threadIdx.x;
    if (i < n) atomicAdd(&g_cnt[bidx[i]], 1.f);
}

__global__ void k_final(const float* __restrict__ wd, const float* __restrict__ bd,
                        float* __restrict__ out) {
    __shared__ float w[HID];
    int t = threadIdx.x;  // 512
    if (t < HID) w[t] = wd[t];
    __syncthreads();
    float icnt = 1.f / fmaxf(g_cnt[t], 1.f);
    float s = bd[0];
#pragma unroll 8
    for (int k = 0; k < HID; k++) s += g_pool[t * HID + k] * icnt * w[k];
    out[t] = 1.f / (1.f + __expf(-s));
}

// ---------------- host launcher ---------------------------------------------
extern "C" void kernel_launch(void* const* d_in, const int* in_sizes, int n_in,
                              void* d_out, int out_size) {
    const float* x    = (const float*)d_in[0];
    const int*   ei   = (const int*)d_in[1];    // int32 (JAX x64 disabled)
    const int*   bidx = (const int*)d_in[2];    // int32
    const float* w_src = (const float*)d_in[3];
    const float* b_src = (const float*)d_in[4];
    const float* w_dst = (const float*)d_in[5];
    const float* b_dst = (const float*)d_in[6];
    // layers: 7..12, 13..18, 19..24 : w1,b1,g,be,w2,b2
    const float* w_dense = (const float*)d_in[25];
    const float* b_dense = (const float*)d_in[26];
    float* out = (float*)d_out;

    int n = in_sizes[0] / N_FEATS;
    int E = in_sizes[1] / 2;

    void *p_deg, *p_bnsum, *p_bnsq, *p_pool, *p_cnt;
    void *p_xsrc, *p_xdst, *p_y, *p_z, *p_h;
    cudaGetSymbolAddress(&p_deg, g_deg);
    cudaGetSymbolAddress(&p_bnsum, g_bnsum);
    cudaGetSymbolAddress(&p_bnsq, g_bnsq);
    cudaGetSymbolAddress(&p_pool, g_pool);
    cudaGetSymbolAddress(&p_cnt, g_cnt);
    cudaGetSymbolAddress(&p_xsrc, g_xsrc);
    cudaGetSymbolAddress(&p_xdst, g_xdst);
    cudaGetSymbolAddress(&p_y, g_y);
    cudaGetSymbolAddress(&p_z, g_z);
    cudaGetSymbolAddress(&p_h, g_h);

    // ---- CSR build (edge_index is identical across layers) ----
    cudaMemsetAsync(p_deg, 0, (size_t)n * sizeof(int), 0);
    k_hist<<<(E + 255) / 256, 256>>>(ei, E);
    k_scan<<<1, 1024>>>(n);
    k_scatter<<<(E + 255) / 256, 256>>>(ei, E);

    // ---- input projections ----
    k_inproj<<<(n * HID + 255) / 256, 256>>>(x, w_src, b_src, w_dst, b_dst, n);

    int aggr_blocks = (n * 32 + 255) / 256;
    int gemm_blocks = (n + 63) / 64;
    float inv_n = 1.f / (float)n;

    for (int layer = 0; layer < 3; layer++) {
        const float* w1 = (const float*)d_in[7 + 6 * layer + 0];
        const float* b1 = (const float*)d_in[7 + 6 * layer + 1];
        const float* gm = (const float*)d_in[7 + 6 * layer + 2];
        const float* be = (const float*)d_in[7 + 6 * layer + 3];
        const float* w2 = (const float*)d_in[7 + 6 * layer + 4];
        const float* b2 = (const float*)d_in[7 + 6 * layer + 5];

        const float* fsrc = (layer == 0) ? (const float*)p_xsrc : (const float*)p_h;
        const float* fdst = (layer == 0) ? (const float*)p_xdst : (const float*)p_h;

        k_aggr<<<aggr_blocks, 256>>>(fsrc, fdst, (float*)p_y, n);
        k_gemm1<<<gemm_blocks, 256>>>((const float*)p_y, w1, b1, (float*)p_z, n);
        cudaMemsetAsync(p_bnsum, 0, HID2 * sizeof(float), 0);
        cudaMemsetAsync(p_bnsq, 0, HID2 * sizeof(float), 0);
        k_stats<<<256, HID2>>>((const float*)p_z, n);
        k_bnfin<<<1, HID2>>>(gm, be, inv_n);
        k_gemm2<<<gemm_blocks, 256>>>((const float*)p_z, w2, b2, (float*)p_h, n);
    }

    // ---- pooling + dense + sigmoid ----
    cudaMemsetAsync(p_pool, 0, NG * HID * sizeof(float), 0);
    cudaMemsetAsync(p_cnt, 0, NG * sizeof(float), 0);
    k_pool<<<(n * 32 + 255) / 256, 256>>>(bidx, n);
    k_cnt<<<(n + 255) / 256, 256>>>(bidx, n);
    k_final<<<1, NG>>>(w_dense, b_dense, out);
}

// round 3
// speedup vs baseline: 1.3976x; 1.3976x over previous
#include <cuda_runtime.h>
#include <math.h>
#include <stdint.h>

#define N_NODES 100000
#define N_EDGES 1600000
#define N_FEATS 9
#define HID 64
#define HID2 128
#define NG 512
#define EPS_MSG 1e-7f
#define BN_EPS 1e-5f

// ---------------- scratch (static device globals; no runtime alloc) ----------
__device__ int   g_sorted_src[N_EDGES];
__device__ int   g_deg[N_NODES];
__device__ int   g_rowptr[N_NODES + 1];
__device__ int   g_cursor[N_NODES];
__device__ float g_xsrc[N_NODES * HID];
__device__ float g_xdst[N_NODES * HID];
__device__ float g_y[N_NODES * HID];
__device__ float g_z[(size_t)N_NODES * HID2];
__device__ float g_h[N_NODES * HID];
__device__ float g_bnsum[HID2];
__device__ float g_bnsq[HID2];
__device__ float g_scale[HID2];
__device__ float g_shift[HID2];
__device__ float g_pool[NG * HID];
__device__ float g_cnt[NG];

// ---------------- tf32 helpers ----------------------------------------------
__device__ __forceinline__ float to_tf32(float x) {
    uint32_t u;
    asm("cvt.rna.tf32.f32 %0, %1;" : "=r"(u) : "f"(x));
    return __uint_as_float(u);
}

__device__ __forceinline__ void mma_tf32(float* d, float a0, float a1, float a2, float a3,
                                         float b0, float b1) {
    asm volatile(
        "mma.sync.aligned.m16n8k8.row.col.f32.tf32.tf32.f32 "
        "{%0,%1,%2,%3}, {%4,%5,%6,%7}, {%8,%9}, {%0,%1,%2,%3};\n"
        : "+f"(d[0]), "+f"(d[1]), "+f"(d[2]), "+f"(d[3])
        : "r"(__float_as_uint(a0)), "r"(__float_as_uint(a1)),
          "r"(__float_as_uint(a2)), "r"(__float_as_uint(a3)),
          "r"(__float_as_uint(b0)), "r"(__float_as_uint(b1)));
}

// ---------------- CSR build ------------------------------------------------
__global__ void k_hist(const int* __restrict__ ei, int E) {
    int e = blockIdx.x * blockDim.x + threadIdx.x;
    if (e >= E) return;
    atomicAdd(&g_deg[ei[E + e]], 1);
}

__global__ void k_scan(int n) {
    __shared__ int part[1024];
    int tid = threadIdx.x;
    int chunk = (n + 1023) >> 10;
    int start = tid * chunk;
    int end = min(start + chunk, n);
    int s = 0;
    for (int i = start; i < end; i++) s += g_deg[i];
    part[tid] = s;
    __syncthreads();
    for (int d = 1; d < 1024; d <<= 1) {
        int v = part[tid];
        int a = (tid >= d) ? part[tid - d] : 0;
        __syncthreads();
        part[tid] = v + a;
        __syncthreads();
    }
    int off = part[tid] - s;
    for (int i = start; i < end; i++) {
        g_rowptr[i] = off;
        g_cursor[i] = off;
        off += g_deg[i];
    }
    if (tid == 1023) g_rowptr[n] = part[1023];
}

__global__ void k_scatter(const int* __restrict__ ei, int E) {
    int e = blockIdx.x * blockDim.x + threadIdx.x;
    if (e >= E) return;
    int s = ei[e];
    int d = ei[E + e];
    int p = atomicAdd(&g_cursor[d], 1);
    g_sorted_src[p] = s;
}

// ---------------- input projection ------------------------------------------
__global__ void k_inproj(const float* __restrict__ x,
                         const float* __restrict__ wsrc, const float* __restrict__ bsrc,
                         const float* __restrict__ wdst, const float* __restrict__ bdst,
                         int n) {
    int idx = blockIdx.x * blockDim.x + threadIdx.x;
    if (idx >= n * HID) return;
    int node = idx >> 6;
    int c = idx & 63;
    const float* xr = x + (size_t)node * N_FEATS;
    float a = bsrc[c], b = bdst[c];
#pragma unroll
    for (int k = 0; k < N_FEATS; k++) {
        float xv = xr[k];
        a += xv * wsrc[k * HID + c];
        b += xv * wdst[k * HID + c];
    }
    g_xsrc[idx] = a;
    g_xdst[idx] = b;
}

// ---------------- softmax aggregation: warp per dst node ---------------------
__global__ void k_aggr(const float* __restrict__ fsrc,
                       const float* __restrict__ fdst,
                       float* __restrict__ y, int n) {
    int warp = (blockIdx.x * blockDim.x + threadIdx.x) >> 5;
    int lane = threadIdx.x & 31;
    if (warp >= n) return;
    int beg = g_rowptr[warp], end = g_rowptr[warp + 1];
    int c = lane * 2;
    float s0 = 0.f, s1 = 0.f, t0 = 0.f, t1 = 0.f;
    for (int i = beg; i < end; i++) {
        int src = __ldg(&g_sorted_src[i]);
        float2 v = *(const float2*)(fsrc + (size_t)src * HID + c);
        float v0 = fmaxf(v.x, 0.f) + EPS_MSG;
        float v1 = fmaxf(v.y, 0.f) + EPS_MSG;
        float e0 = __expf(v0);
        float e1 = __expf(v1);
        s0 += e0; t0 += e0 * v0;
        s1 += e1; t1 += e1 * v1;
    }
    float2 dv = *(const float2*)(fdst + (size_t)warp * HID + c);
    float2 o;
    o.x = t0 / (s0 + 1e-16f) + dv.x;
    o.y = t1 / (s1 + 1e-16f) + dv.y;
    *(float2*)(y + (size_t)warp * HID + c) = o;
}

// ---------------- GEMM1 (tf32 tensor): z = y[N,64] @ w1[64,128] + b1 --------
// 64x64 output tile per block (grid.y = 2 n-tiles). 256 thr = 8 warps:
// warp w -> m-band (w&3)*16, n-half (w>>2)*32 (4 n8-tiles).
__global__ void k_gemm1_t(const float* __restrict__ y,
                          const float* __restrict__ w1, const float* __restrict__ b1,
                          float* __restrict__ z, int n) {
    __shared__ float As[64][68];  // [m][k], stride 68 -> conflict-free frag reads
    __shared__ float Bs[64][72];  // [k][n], stride 72 -> conflict-free frag reads
    int t = threadIdx.x;
    int row0 = blockIdx.x * 64;
    int n0 = blockIdx.y * 64;

    for (int i = t * 4; i < 64 * 64; i += 1024) {
        int r = i >> 6, c = i & 63;
        float4 v = make_float4(0.f, 0.f, 0.f, 0.f);
        if (row0 + r < n) v = *(const float4*)(y + (size_t)(row0 + r) * HID + c);
        float4 o;
        o.x = to_tf32(v.x); o.y = to_tf32(v.y); o.z = to_tf32(v.z); o.w = to_tf32(v.w);
        *(float4*)(&As[r][c]) = o;
    }
    for (int i = t * 4; i < 64 * 64; i += 1024) {
        int k = i >> 6, c = i & 63;
        float4 v = *(const float4*)(w1 + (size_t)k * HID2 + n0 + c);
        float4 o;
        o.x = to_tf32(v.x); o.y = to_tf32(v.y); o.z = to_tf32(v.z); o.w = to_tf32(v.w);
        *(float4*)(&Bs[k][c]) = o;
    }
    __syncthreads();

    int w = t >> 5, l = t & 31;
    int band = (w & 3) * 16;
    int nh = (w >> 2) * 32;
    int lq = l >> 2, lr = l & 3;

    float acc[4][4];
#pragma unroll
    for (int i = 0; i < 4; i++)
#pragma unroll
        for (int j = 0; j < 4; j++) acc[i][j] = 0.f;

#pragma unroll
    for (int ks = 0; ks < 8; ks++) {
        int k = ks * 8;
        float a0 = As[band + lq][k + lr];
        float a1 = As[band + lq + 8][k + lr];
        float a2 = As[band + lq][k + lr + 4];
        float a3 = As[band + lq + 8][k + lr + 4];
#pragma unroll
        for (int tj = 0; tj < 4; tj++) {
            float b0 = Bs[k + lr][nh + tj * 8 + lq];
            float bb = Bs[k + lr + 4][nh + tj * 8 + lq];
            mma_tf32(acc[tj], a0, a1, a2, a3, b0, bb);
        }
    }

    int rA = row0 + band + lq;
    int rB = rA + 8;
#pragma unroll
    for (int tj = 0; tj < 4; tj++) {
        int col = n0 + nh + tj * 8 + 2 * lr;
        float bx = __ldg(b1 + col), by = __ldg(b1 + col + 1);
        if (rA < n) {
            float2 o; o.x = acc[tj][0] + bx; o.y = acc[tj][1] + by;
            *(float2*)(z + (size_t)rA * HID2 + col) = o;
        }
        if (rB < n) {
            float2 o; o.x = acc[tj][2] + bx; o.y = acc[tj][3] + by;
            *(float2*)(z + (size_t)rB * HID2 + col) = o;
        }
    }
}

// ---------------- BN stats / finalize -----------------------------------------
__global__ void k_stats(const float* __restrict__ z, int n) {
    int c = threadIdx.x;  // 128
    float s = 0.f, q = 0.f;
    for (int r = blockIdx.x; r < n; r += gridDim.x) {
        float v = z[(size_t)r * HID2 + c];
        s += v;
        q += v * v;
    }
    atomicAdd(&g_bnsum[c], s);
    atomicAdd(&g_bnsq[c], q);
}

__global__ void k_bnfin(const float* __restrict__ gma, const float* __restrict__ bet, float inv_n) {
    int c = threadIdx.x;
    float mu = g_bnsum[c] * inv_n;
    float var = g_bnsq[c] * inv_n - mu * mu;
    float sc = gma[c] * rsqrtf(var + BN_EPS);
    g_scale[c] = sc;
    g_shift[c] = bet[c] - mu * sc;
}

// ---------------- GEMM2 (tf32): h = relu( relu(BN(z)) @ w2[128,64] + b2 ) ----
// 64x64 output tile, K=128 staged in two 64-chunks.
__global__ void k_gemm2_t(const float* __restrict__ z,
                          const float* __restrict__ w2, const float* __restrict__ b2,
                          float* __restrict__ h, int n) {
    __shared__ float As[64][68];
    __shared__ float Bs[64][72];
    int t = threadIdx.x;
    int row0 = blockIdx.x * 64;
    int w = t >> 5, l = t & 31;
    int band = (w & 3) * 16;
    int nh = (w >> 2) * 32;
    int lq = l >> 2, lr = l & 3;

    float acc[4][4];
#pragma unroll
    for (int i = 0; i < 4; i++)
#pragma unroll
        for (int j = 0; j < 4; j++) acc[i][j] = 0.f;

    for (int k0 = 0; k0 < HID2; k0 += 64) {
        __syncthreads();
        for (int i = t * 4; i < 64 * 64; i += 1024) {
            int r = i >> 6, c = i & 63;
            float4 v = make_float4(0.f, 0.f, 0.f, 0.f);
            if (row0 + r < n) v = *(const float4*)(z + (size_t)(row0 + r) * HID2 + k0 + c);
            float4 sc = *(const float4*)(&g_scale[k0 + c]);
            float4 sh = *(const float4*)(&g_shift[k0 + c]);
            float4 o;
            o.x = to_tf32(fmaxf(v.x * sc.x + sh.x, 0.f));
            o.y = to_tf32(fmaxf(v.y * sc.y + sh.y, 0.f));
            o.z = to_tf32(fmaxf(v.z * sc.z + sh.z, 0.f));
            o.w = to_tf32(fmaxf(v.w * sc.w + sh.w, 0.f));
            *(float4*)(&As[r][c]) = o;
        }
        for (int i = t * 4; i < 64 * 64; i += 1024) {
            int k = i >> 6, c = i & 63;
            float4 v = *(const float4*)(w2 + (size_t)(k0 + k) * HID + c);
            float4 o;
            o.x = to_tf32(v.x); o.y = to_tf32(v.y); o.z = to_tf32(v.z); o.w = to_tf32(v.w);
            *(float4*)(&Bs[k][c]) = o;
        }
        __syncthreads();

#pragma unroll
        for (int ks = 0; ks < 8; ks++) {
            int k = ks * 8;
            float a0 = As[band + lq][k + lr];
            float a1 = As[band + lq + 8][k + lr];
            float a2 = As[band + lq][k + lr + 4];
            float a3 = As[band + lq + 8][k + lr + 4];
#pragma unroll
            for (int tj = 0; tj < 4; tj++) {
                float b0 = Bs[k + lr][nh + tj * 8 + lq];
                float bb = Bs[k + lr + 4][nh + tj * 8 + lq];
                mma_tf32(acc[tj], a0, a1, a2, a3, b0, bb);
            }
        }
    }

    int rA = row0 + band + lq;
    int rB = rA + 8;
#pragma unroll
    for (int tj = 0; tj < 4; tj++) {
        int col = nh + tj * 8 + 2 * lr;
        float bx = __ldg(b2 + col), by = __ldg(b2 + col + 1);
        if (rA < n) {
            float2 o;
            o.x = fmaxf(acc[tj][0] + bx, 0.f);
            o.y = fmaxf(acc[tj][1] + by, 0.f);
            *(float2*)(h + (size_t)rA * HID + col) = o;
        }
        if (rB < n) {
            float2 o;
            o.x = fmaxf(acc[tj][2] + bx, 0.f);
            o.y = fmaxf(acc[tj][3] + by, 0.f);
            *(float2*)(h + (size_t)rB * HID + col) = o;
        }
    }
}

// ---------------- pooling + head ----------------------------------------------
__global__ void k_pool(const int* __restrict__ bidx, int n) {
    int idx = blockIdx.x * blockDim.x + threadIdx.x;
    if (idx >= n * 32) return;
    int node = idx >> 5;
    int c2 = (idx & 31) * 2;
    int g = bidx[node];
    float2 v = *(const float2*)(g_h + (size_t)node * HID + c2);
    atomicAdd(&g_pool[g * HID + c2], v.x);
    atomicAdd(&g_pool[g * HID + c2 + 1], v.y);
}

__global__ void k_cnt(const int* __restrict__ bidx, int n) {
    int i = blockIdx.x * blockDim.x + threadIdx.x;
    if (i < n) atomicAdd(&g_cnt[bidx[i]], 1.f);
}

__global__ void k_final(const float* __restrict__ wd, const float* __restrict__ bd,
                        float* __restrict__ out) {
    __shared__ float w[HID];
    int t = threadIdx.x;  // 512
    if (t < HID) w[t] = wd[t];
    __syncthreads();
    float icnt = 1.f / fmaxf(g_cnt[t], 1.f);
    float s = bd[0];
#pragma unroll 8
    for (int k = 0; k < HID; k++) s += g_pool[t * HID + k] * icnt * w[k];
    out[t] = 1.f / (1.f + __expf(-s));
}

// ---------------- host launcher -------------------------------------------------
extern "C" void kernel_launch(void* const* d_in, const int* in_sizes, int n_in,
                              void* d_out, int out_size) {
    const float* x    = (const float*)d_in[0];
    const int*   ei   = (const int*)d_in[1];
    const int*   bidx = (const int*)d_in[2];
    const float* w_src = (const float*)d_in[3];
    const float* b_src = (const float*)d_in[4];
    const float* w_dst = (const float*)d_in[5];
    const float* b_dst = (const float*)d_in[6];
    const float* w_dense = (const float*)d_in[25];
    const float* b_dense = (const float*)d_in[26];
    float* out = (float*)d_out;

    int n = in_sizes[0] / N_FEATS;
    int E = in_sizes[1] / 2;

    void *p_deg, *p_bnsum, *p_bnsq, *p_pool, *p_cnt;
    void *p_xsrc, *p_xdst, *p_y, *p_z, *p_h;
    cudaGetSymbolAddress(&p_deg, g_deg);
    cudaGetSymbolAddress(&p_bnsum, g_bnsum);
    cudaGetSymbolAddress(&p_bnsq, g_bnsq);
    cudaGetSymbolAddress(&p_pool, g_pool);
    cudaGetSymbolAddress(&p_cnt, g_cnt);
    cudaGetSymbolAddress(&p_xsrc, g_xsrc);
    cudaGetSymbolAddress(&p_xdst, g_xdst);
    cudaGetSymbolAddress(&p_y, g_y);
    cudaGetSymbolAddress(&p_z, g_z);
    cudaGetSymbolAddress(&p_h, g_h);

    // ---- CSR build ----
    cudaMemsetAsync(p_deg, 0, (size_t)n * sizeof(int), 0);
    k_hist<<<(E + 255) / 256, 256>>>(ei, E);
    k_scan<<<1, 1024>>>(n);
    k_scatter<<<(E + 255) / 256, 256>>>(ei, E);

    // ---- input projections ----
    k_inproj<<<(n * HID + 255) / 256, 256>>>(x, w_src, b_src, w_dst, b_dst, n);

    int aggr_blocks = (n * 32 + 255) / 256;
    dim3 g1_grid((n + 63) / 64, 2);
    int g2_grid = (n + 63) / 64;
    float inv_n = 1.f / (float)n;

    for (int layer = 0; layer < 3; layer++) {
        const float* w1 = (const float*)d_in[7 + 6 * layer + 0];
        const float* b1 = (const float*)d_in[7 + 6 * layer + 1];
        const float* gm = (const float*)d_in[7 + 6 * layer + 2];
        const float* be = (const float*)d_in[7 + 6 * layer + 3];
        const float* w2 = (const float*)d_in[7 + 6 * layer + 4];
        const float* b2 = (const float*)d_in[7 + 6 * layer + 5];

        const float* fsrc = (layer == 0) ? (const float*)p_xsrc : (const float*)p_h;
        const float* fdst = (layer == 0) ? (const float*)p_xdst : (const float*)p_h;

        k_aggr<<<aggr_blocks, 256>>>(fsrc, fdst, (float*)p_y, n);
        k_gemm1_t<<<g1_grid, 256>>>((const float*)p_y, w1, b1, (float*)p_z, n);
        cudaMemsetAsync(p_bnsum, 0, HID2 * sizeof(float), 0);
        cudaMemsetAsync(p_bnsq, 0, HID2 * sizeof(float), 0);
        k_stats<<<512, HID2>>>((const float*)p_z, n);
        k_bnfin<<<1, HID2>>>(gm, be, inv_n);
        k_gemm2_t<<<g2_grid, 256>>>((const float*)p_z, w2, b2, (float*)p_h, n);
    }

    // ---- pooling + dense + sigmoid ----
    cudaMemsetAsync(p_pool, 0, NG * HID * sizeof(float), 0);
    cudaMemsetAsync(p_cnt, 0, NG * sizeof(float), 0);
    k_pool<<<(n * 32 + 255) / 256, 256>>>(bidx, n);
    k_cnt<<<(n + 255) / 256, 256>>>(bidx, n);
    k_final<<<1, NG>>>(w_dense, b_dense, out);
}

// round 4
// speedup vs baseline: 1.7295x; 1.2375x over previous
#include <cuda_runtime.h>
#include <math.h>
#include <stdint.h>

#define N_NODES 100000
#define N_EDGES 1600000
#define N_FEATS 9
#define HID 64
#define HID2 128
#define NG 512
#define EPS_MSG 1e-7f
#define BN_EPS 1e-5f

// ---------------- scratch (static device globals; no runtime alloc) ----------
__device__ int   g_sorted_src[N_EDGES];
__device__ int   g_deg[N_NODES];
__device__ int   g_rowptr[N_NODES + 1];
__device__ int   g_cursor[N_NODES];
__device__ float g_xsrc[N_NODES * HID];
__device__ float g_xdst[N_NODES * HID];
__device__ float g_y[N_NODES * HID];
__device__ float g_z[(size_t)N_NODES * HID2];
__device__ float g_h[N_NODES * HID];
__device__ float g_bnsum[HID2];   // cleared by k_bnfin each layer
__device__ float g_bnsq[HID2];
__device__ float g_scale[HID2];
__device__ float g_shift[HID2];
__device__ float g_pool[NG * HID]; // cleared by k_final each call
__device__ float g_cnt[NG];

// ---------------- tf32 helpers ----------------------------------------------
__device__ __forceinline__ float to_tf32(float x) {
    uint32_t u;
    asm("cvt.rna.tf32.f32 %0, %1;" : "=r"(u) : "f"(x));
    return __uint_as_float(u);
}

__device__ __forceinline__ void mma_tf32(float* d, float a0, float a1, float a2, float a3,
                                         float b0, float b1) {
    asm volatile(
        "mma.sync.aligned.m16n8k8.row.col.f32.tf32.tf32.f32 "
        "{%0,%1,%2,%3}, {%4,%5,%6,%7}, {%8,%9}, {%0,%1,%2,%3};\n"
        : "+f"(d[0]), "+f"(d[1]), "+f"(d[2]), "+f"(d[3])
        : "r"(__float_as_uint(a0)), "r"(__float_as_uint(a1)),
          "r"(__float_as_uint(a2)), "r"(__float_as_uint(a3)),
          "r"(__float_as_uint(b0)), "r"(__float_as_uint(b1)));
}

// ---------------- CSR build ------------------------------------------------
__global__ void k_hist(const int* __restrict__ ei, int E) {
    int e = blockIdx.x * blockDim.x + threadIdx.x;
    if (e >= E) return;
    atomicAdd(&g_deg[ei[E + e]], 1);
}

__global__ void k_scan(int n) {
    __shared__ int part[1024];
    int tid = threadIdx.x;
    int chunk = (n + 1023) >> 10;
    int start = tid * chunk;
    int end = min(start + chunk, n);
    int s = 0;
    for (int i = start; i < end; i++) s += g_deg[i];
    part[tid] = s;
    __syncthreads();
    for (int d = 1; d < 1024; d <<= 1) {
        int v = part[tid];
        int a = (tid >= d) ? part[tid - d] : 0;
        __syncthreads();
        part[tid] = v + a;
        __syncthreads();
    }
    int off = part[tid] - s;
    for (int i = start; i < end; i++) {
        g_rowptr[i] = off;
        g_cursor[i] = off;
        off += g_deg[i];
    }
    if (tid == 1023) g_rowptr[n] = part[1023];
}

__global__ void k_scatter(const int* __restrict__ ei, int E) {
    int e = blockIdx.x * blockDim.x + threadIdx.x;
    if (e >= E) return;
    int s = ei[e];
    int d = ei[E + e];
    int p = atomicAdd(&g_cursor[d], 1);
    g_sorted_src[p] = s;
}

// ---------------- input projection (16 thr/node, float4) ---------------------
__global__ void k_inproj(const float* __restrict__ x,
                         const float* __restrict__ wsrc, const float* __restrict__ bsrc,
                         const float* __restrict__ wdst, const float* __restrict__ bdst,
                         int n) {
    int idx = blockIdx.x * blockDim.x + threadIdx.x;
    if (idx >= n * 16) return;
    int node = idx >> 4;
    int c = (idx & 15) << 2;
    const float* xr = x + (size_t)node * N_FEATS;
    float4 a = *(const float4*)(bsrc + c);
    float4 b = *(const float4*)(bdst + c);
#pragma unroll
    for (int k = 0; k < N_FEATS; k++) {
        float xv = __ldg(xr + k);
        float4 ws = *(const float4*)(wsrc + k * HID + c);
        float4 wd = *(const float4*)(wdst + k * HID + c);
        a.x += xv * ws.x; a.y += xv * ws.y; a.z += xv * ws.z; a.w += xv * ws.w;
        b.x += xv * wd.x; b.y += xv * wd.y; b.z += xv * wd.z; b.w += xv * wd.w;
    }
    *(float4*)(g_xsrc + (size_t)node * HID + c) = a;
    *(float4*)(g_xdst + (size_t)node * HID + c) = b;
}

// ---------------- softmax aggregation: warp per dst node ---------------------
// indices lane-distributed then shfl-broadcast; inner loop unrolled for MLP
__global__ void k_aggr(const float* __restrict__ fsrc,
                       const float* __restrict__ fdst,
                       float* __restrict__ y, int n) {
    int warp = (blockIdx.x * blockDim.x + threadIdx.x) >> 5;
    int lane = threadIdx.x & 31;
    if (warp >= n) return;
    int beg = g_rowptr[warp], end = g_rowptr[warp + 1];
    int c = lane * 2;
    float s0 = 0.f, s1 = 0.f, t0 = 0.f, t1 = 0.f;
    for (int base = beg; base < end; base += 32) {
        int m = end - base;
        if (m > 32) m = 32;
        int myidx = (lane < m) ? __ldg(&g_sorted_src[base + lane]) : 0;
#pragma unroll 4
        for (int j = 0; j < m; j++) {
            int src = __shfl_sync(0xffffffffu, myidx, j);
            float2 v = *(const float2*)(fsrc + (size_t)src * HID + c);
            float v0 = fmaxf(v.x, 0.f) + EPS_MSG;
            float v1 = fmaxf(v.y, 0.f) + EPS_MSG;
            float e0 = __expf(v0);
            float e1 = __expf(v1);
            s0 += e0; t0 += e0 * v0;
            s1 += e1; t1 += e1 * v1;
        }
    }
    float2 dv = *(const float2*)(fdst + (size_t)warp * HID + c);
    float2 o;
    o.x = t0 / (s0 + 1e-16f) + dv.x;
    o.y = t1 / (s1 + 1e-16f) + dv.y;
    *(float2*)(y + (size_t)warp * HID + c) = o;
}

// ---------------- GEMM1 (tf32): z = y[N,64] @ w1[64,128] + b1, fused BN stats
__global__ void k_gemm1_t(const float* __restrict__ y,
                          const float* __restrict__ w1, const float* __restrict__ b1,
                          float* __restrict__ z, int n) {
    __shared__ float As[64][68];
    __shared__ float Bs[64][72];
    __shared__ float ssum[64], ssq[64];
    int t = threadIdx.x;
    int row0 = blockIdx.x * 64;
    int n0 = blockIdx.y * 64;

    if (t < 64) { ssum[t] = 0.f; ssq[t] = 0.f; }
    for (int i = t * 4; i < 64 * 64; i += 1024) {
        int r = i >> 6, c = i & 63;
        float4 v = make_float4(0.f, 0.f, 0.f, 0.f);
        if (row0 + r < n) v = *(const float4*)(y + (size_t)(row0 + r) * HID + c);
        float4 o;
        o.x = to_tf32(v.x); o.y = to_tf32(v.y); o.z = to_tf32(v.z); o.w = to_tf32(v.w);
        *(float4*)(&As[r][c]) = o;
    }
    for (int i = t * 4; i < 64 * 64; i += 1024) {
        int k = i >> 6, c = i & 63;
        float4 v = *(const float4*)(w1 + (size_t)k * HID2 + n0 + c);
        float4 o;
        o.x = to_tf32(v.x); o.y = to_tf32(v.y); o.z = to_tf32(v.z); o.w = to_tf32(v.w);
        *(float4*)(&Bs[k][c]) = o;
    }
    __syncthreads();

    int w = t >> 5, l = t & 31;
    int band = (w & 3) * 16;
    int nh = (w >> 2) * 32;
    int lq = l >> 2, lr = l & 3;

    float acc[4][4];
#pragma unroll
    for (int i = 0; i < 4; i++)
#pragma unroll
        for (int j = 0; j < 4; j++) acc[i][j] = 0.f;

#pragma unroll
    for (int ks = 0; ks < 8; ks++) {
        int k = ks * 8;
        float a0 = As[band + lq][k + lr];
        float a1 = As[band + lq + 8][k + lr];
        float a2 = As[band + lq][k + lr + 4];
        float a3 = As[band + lq + 8][k + lr + 4];
#pragma unroll
        for (int tj = 0; tj < 4; tj++) {
            float b0 = Bs[k + lr][nh + tj * 8 + lq];
            float bb = Bs[k + lr + 4][nh + tj * 8 + lq];
            mma_tf32(acc[tj], a0, a1, a2, a3, b0, bb);
        }
    }

    int rA = row0 + band + lq;
    int rB = rA + 8;
    bool vA, vB;
    vA = rA < n; vB = rB < n;
#pragma unroll
    for (int tj = 0; tj < 4; tj++) {
        int colL = nh + tj * 8 + 2 * lr;
        int col = n0 + colL;
        float bx = __ldg(b1 + col), by = __ldg(b1 + col + 1);
        float oAx = acc[tj][0] + bx, oAy = acc[tj][1] + by;
        float oBx = acc[tj][2] + bx, oBy = acc[tj][3] + by;
        if (vA) { float2 o; o.x = oAx; o.y = oAy; *(float2*)(z + (size_t)rA * HID2 + col) = o; }
        if (vB) { float2 o; o.x = oBx; o.y = oBy; *(float2*)(z + (size_t)rB * HID2 + col) = o; }
        // BN statistics: per-column sums over this warp's 16-row band
        float sx = (vA ? oAx : 0.f) + (vB ? oBx : 0.f);
        float sy = (vA ? oAy : 0.f) + (vB ? oBy : 0.f);
        float qx = (vA ? oAx * oAx : 0.f) + (vB ? oBx * oBx : 0.f);
        float qy = (vA ? oAy * oAy : 0.f) + (vB ? oBy * oBy : 0.f);
#pragma unroll
        for (int off = 4; off < 32; off <<= 1) {
            sx += __shfl_xor_sync(0xffffffffu, sx, off);
            sy += __shfl_xor_sync(0xffffffffu, sy, off);
            qx += __shfl_xor_sync(0xffffffffu, qx, off);
            qy += __shfl_xor_sync(0xffffffffu, qy, off);
        }
        if (lq == 0) {
            atomicAdd(&ssum[colL], sx);
            atomicAdd(&ssum[colL + 1], sy);
            atomicAdd(&ssq[colL], qx);
            atomicAdd(&ssq[colL + 1], qy);
        }
    }
    __syncthreads();
    if (t < 64) {
        atomicAdd(&g_bnsum[n0 + t], ssum[t]);
        atomicAdd(&g_bnsq[n0 + t], ssq[t]);
    }
}

// ---------------- BN finalize (self-clearing accumulators) -------------------
__global__ void k_bnfin(const float* __restrict__ gma, const float* __restrict__ bet, float inv_n) {
    int c = threadIdx.x;
    float mu = g_bnsum[c] * inv_n;
    float var = g_bnsq[c] * inv_n - mu * mu;
    float sc = gma[c] * rsqrtf(var + BN_EPS);
    g_scale[c] = sc;
    g_shift[c] = bet[c] - mu * sc;
    g_bnsum[c] = 0.f;   // ready for next layer's GEMM1 atomics
    g_bnsq[c] = 0.f;
}

// ---------------- GEMM2 (tf32): h = relu( relu(BN(z)) @ w2 + b2 ) ------------
// LAST layer: fused mean-pool accumulation instead of writing h.
template <bool LAST>
__global__ void k_gemm2_t(const float* __restrict__ z,
                          const float* __restrict__ w2, const float* __restrict__ b2,
                          float* __restrict__ h, const int* __restrict__ bidx, int n) {
    __shared__ float As[64][68];
    __shared__ float Bs[64][72];
    int t = threadIdx.x;
    int row0 = blockIdx.x * 64;
    int w = t >> 5, l = t & 31;
    int band = (w & 3) * 16;
    int nh = (w >> 2) * 32;
    int lq = l >> 2, lr = l & 3;

    float acc[4][4];
#pragma unroll
    for (int i = 0; i < 4; i++)
#pragma unroll
        for (int j = 0; j < 4; j++) acc[i][j] = 0.f;

    for (int k0 = 0; k0 < HID2; k0 += 64) {
        __syncthreads();
        for (int i = t * 4; i < 64 * 64; i += 1024) {
            int r = i >> 6, c = i & 63;
            float4 v = make_float4(0.f, 0.f, 0.f, 0.f);
            if (row0 + r < n) v = *(const float4*)(z + (size_t)(row0 + r) * HID2 + k0 + c);
            float4 sc = *(const float4*)(&g_scale[k0 + c]);
            float4 sh = *(const float4*)(&g_shift[k0 + c]);
            float4 o;
            o.x = to_tf32(fmaxf(v.x * sc.x + sh.x, 0.f));
            o.y = to_tf32(fmaxf(v.y * sc.y + sh.y, 0.f));
            o.z = to_tf32(fmaxf(v.z * sc.z + sh.z, 0.f));
            o.w = to_tf32(fmaxf(v.w * sc.w + sh.w, 0.f));
            *(float4*)(&As[r][c]) = o;
        }
        for (int i = t * 4; i < 64 * 64; i += 1024) {
            int k = i >> 6, c = i & 63;
            float4 v = *(const float4*)(w2 + (size_t)(k0 + k) * HID + c);
            float4 o;
            o.x = to_tf32(v.x); o.y = to_tf32(v.y); o.z = to_tf32(v.z); o.w = to_tf32(v.w);
            *(float4*)(&Bs[k][c]) = o;
        }
        __syncthreads();

#pragma unroll
        for (int ks = 0; ks < 8; ks++) {
            int k = ks * 8;
            float a0 = As[band + lq][k + lr];
            float a1 = As[band + lq + 8][k + lr];
            float a2 = As[band + lq][k + lr + 4];
            float a3 = As[band + lq + 8][k + lr + 4];
#pragma unroll
            for (int tj = 0; tj < 4; tj++) {
                float b0 = Bs[k + lr][nh + tj * 8 + lq];
                float bb = Bs[k + lr + 4][nh + tj * 8 + lq];
                mma_tf32(acc[tj], a0, a1, a2, a3, b0, bb);
            }
        }
    }

    int rA = row0 + band + lq;
    int rB = rA + 8;
    bool vA = rA < n, vB = rB < n;
    int gA = 0, gB = 0;
    if (LAST) {
        if (vA) gA = __ldg(&bidx[rA]);
        if (vB) gB = __ldg(&bidx[rB]);
        if (nh == 0 && lr == 0) {  // count each row exactly once
            if (vA) atomicAdd(&g_cnt[gA], 1.f);
            if (vB) atomicAdd(&g_cnt[gB], 1.f);
        }
    }
#pragma unroll
    for (int tj = 0; tj < 4; tj++) {
        int col = nh + tj * 8 + 2 * lr;
        float bx = __ldg(b2 + col), by = __ldg(b2 + col + 1);
        float oAx = fmaxf(acc[tj][0] + bx, 0.f);
        float oAy = fmaxf(acc[tj][1] + by, 0.f);
        float oBx = fmaxf(acc[tj][2] + bx, 0.f);
        float oBy = fmaxf(acc[tj][3] + by, 0.f);
        if (LAST) {
            if (vA) {
                atomicAdd(&g_pool[gA * HID + col], oAx);
                atomicAdd(&g_pool[gA * HID + col + 1], oAy);
            }
            if (vB) {
                atomicAdd(&g_pool[gB * HID + col], oBx);
                atomicAdd(&g_pool[gB * HID + col + 1], oBy);
            }
        } else {
            if (vA) { float2 o; o.x = oAx; o.y = oAy; *(float2*)(h + (size_t)rA * HID + col) = o; }
            if (vB) { float2 o; o.x = oBx; o.y = oBy; *(float2*)(h + (size_t)rB * HID + col) = o; }
        }
    }
}

// ---------------- head (self-clearing pool/cnt) -------------------------------
__global__ void k_final(const float* __restrict__ wd, const float* __restrict__ bd,
                        float* __restrict__ out) {
    __shared__ float w[HID];
    int t = threadIdx.x;  // 512
    if (t < HID) w[t] = wd[t];
    __syncthreads();
    float icnt = 1.f / fmaxf(g_cnt[t], 1.f);
    float s = bd[0];
#pragma unroll 8
    for (int k = 0; k < HID; k++) s += g_pool[t * HID + k] * icnt * w[k];
    out[t] = 1.f / (1.f + __expf(-s));
#pragma unroll 8
    for (int k = 0; k < HID; k++) g_pool[t * HID + k] = 0.f;
    g_cnt[t] = 0.f;
}

// ---------------- host launcher -------------------------------------------------
extern "C" void kernel_launch(void* const* d_in, const int* in_sizes, int n_in,
                              void* d_out, int out_size) {
    const float* x    = (const float*)d_in[0];
    const int*   ei   = (const int*)d_in[1];
    const int*   bidx = (const int*)d_in[2];
    const float* w_src = (const float*)d_in[3];
    const float* b_src = (const float*)d_in[4];
    const float* w_dst = (const float*)d_in[5];
    const float* b_dst = (const float*)d_in[6];
    const float* w_dense = (const float*)d_in[25];
    const float* b_dense = (const float*)d_in[26];
    float* out = (float*)d_out;

    int n = in_sizes[0] / N_FEATS;
    int E = in_sizes[1] / 2;

    void *p_deg, *p_xsrc, *p_xdst, *p_y, *p_z, *p_h;
    cudaGetSymbolAddress(&p_deg, g_deg);
    cudaGetSymbolAddress(&p_xsrc, g_xsrc);
    cudaGetSymbolAddress(&p_xdst, g_xdst);
    cudaGetSymbolAddress(&p_y, g_y);
    cudaGetSymbolAddress(&p_z, g_z);
    cudaGetSymbolAddress(&p_h, g_h);

    // ---- CSR build ----
    cudaMemsetAsync(p_deg, 0, (size_t)n * sizeof(int), 0);
    k_hist<<<(E + 255) / 256, 256>>>(ei, E);
    k_scan<<<1, 1024>>>(n);
    k_scatter<<<(E + 255) / 256, 256>>>(ei, E);

    // ---- input projections ----
    k_inproj<<<(n * 16 + 255) / 256, 256>>>(x, w_src, b_src, w_dst, b_dst, n);

    int aggr_blocks = (n * 32 + 255) / 256;
    dim3 g1_grid((n + 63) / 64, 2);
    int g2_grid = (n + 63) / 64;
    float inv_n = 1.f / (float)n;

    for (int layer = 0; layer < 3; layer++) {
        const float* w1 = (const float*)d_in[7 + 6 * layer + 0];
        const float* b1 = (const float*)d_in[7 + 6 * layer + 1];
        const float* gm = (const float*)d_in[7 + 6 * layer + 2];
        const float* be = (const float*)d_in[7 + 6 * layer + 3];
        const float* w2 = (const float*)d_in[7 + 6 * layer + 4];
        const float* b2 = (const float*)d_in[7 + 6 * layer + 5];

        const float* fsrc = (layer == 0) ? (const float*)p_xsrc : (const float*)p_h;
        const float* fdst = (layer == 0) ? (const float*)p_xdst : (const float*)p_h;

        k_aggr<<<aggr_blocks, 256>>>(fsrc, fdst, (float*)p_y, n);
        k_gemm1_t<<<g1_grid, 256>>>((const float*)p_y, w1, b1, (float*)p_z, n);
        k_bnfin<<<1, HID2>>>(gm, be, inv_n);
        if (layer < 2)
            k_gemm2_t<false><<<g2_grid, 256>>>((const float*)p_z, w2, b2, (float*)p_h, bidx, n);
        else
            k_gemm2_t<true><<<g2_grid, 256>>>((const float*)p_z, w2, b2, (float*)p_h, bidx, n);
    }

    k_final<<<1, NG>>>(w_dense, b_dense, out);
}

// round 5
// speedup vs baseline: 2.4487x; 1.4158x over previous
#include <cuda_runtime.h>
#include <math.h>
#include <stdint.h>

#define N_NODES 100000
#define N_EDGES 1600000
#define N_FEATS 9
#define HID 64
#define HID2 128
#define NG 512
#define EPS_MSG 1e-7f
#define BN_EPS 1e-5f
#define SCAN_T 512

// ---------------- scratch (static device globals; zero-init at load) ---------
__device__ int   g_sorted_src[N_EDGES];
__device__ int   g_deg[N_NODES];       // re-zeroed by k_scan_c each call
__device__ int   g_tmp[N_NODES];
__device__ int   g_bsum[256];
__device__ int   g_rowptr[N_NODES + 1];
__device__ int   g_cursor[N_NODES];
__device__ float g_xsrc[N_NODES * HID];
__device__ float g_xdst[N_NODES * HID];
__device__ float g_y[N_NODES * HID];
__device__ float g_z[(size_t)N_NODES * HID2];
__device__ float g_h[N_NODES * HID];
__device__ float g_bnsum[HID2];        // cleared by k_bnfin each layer
__device__ float g_bnsq[HID2];
__device__ float g_scale[HID2];
__device__ float g_shift[HID2];
__device__ float g_pool[NG * HID];     // cleared by k_final each call
__device__ float g_cnt[NG];

// ---------------- tf32 helpers ----------------------------------------------
__device__ __forceinline__ float to_tf32(float x) {
    uint32_t u;
    asm("cvt.rna.tf32.f32 %0, %1;" : "=r"(u) : "f"(x));
    return __uint_as_float(u);
}

__device__ __forceinline__ void mma_tf32(float* d, float a0, float a1, float a2, float a3,
                                         float b0, float b1) {
    asm volatile(
        "mma.sync.aligned.m16n8k8.row.col.f32.tf32.tf32.f32 "
        "{%0,%1,%2,%3}, {%4,%5,%6,%7}, {%8,%9}, {%0,%1,%2,%3};\n"
        : "+f"(d[0]), "+f"(d[1]), "+f"(d[2]), "+f"(d[3])
        : "r"(__float_as_uint(a0)), "r"(__float_as_uint(a1)),
          "r"(__float_as_uint(a2)), "r"(__float_as_uint(a3)),
          "r"(__float_as_uint(b0)), "r"(__float_as_uint(b1)));
}

// ---------------- CSR build ------------------------------------------------
__global__ void k_hist(const int* __restrict__ ei, int E) {
    int e = blockIdx.x * blockDim.x + threadIdx.x;
    if (e >= E) return;
    atomicAdd(&g_deg[ei[E + e]], 1);
}

// per-block inclusive scan: write in-block exclusive prefix + block totals
__global__ void k_scan_a(int n) {
    __shared__ int sh[SCAN_T];
    int tid = threadIdx.x;
    int i = blockIdx.x * SCAN_T + tid;
    int v = (i < n) ? g_deg[i] : 0;
    sh[tid] = v;
    __syncthreads();
#pragma unroll
    for (int d = 1; d < SCAN_T; d <<= 1) {
        int t = sh[tid];
        int a = (tid >= d) ? sh[tid - d] : 0;
        __syncthreads();
        sh[tid] = t + a;
        __syncthreads();
    }
    if (i < n) g_tmp[i] = sh[tid] - v;              // exclusive within block
    if (tid == SCAN_T - 1) g_bsum[blockIdx.x] = sh[tid];
}

// every block re-scans the (<=256) block sums in smem, applies offsets,
// writes rowptr + cursor, and re-zeroes g_deg for the next call
__global__ void k_scan_c(int n) {
    __shared__ int bs[256];
    int tid = threadIdx.x;
    int nb = gridDim.x;
    if (tid < 256) bs[tid] = (tid < nb) ? g_bsum[tid] : 0;
    __syncthreads();
#pragma unroll
    for (int d = 1; d < 256; d <<= 1) {
        int t = 0, a = 0;
        if (tid < 256) { t = bs[tid]; a = (tid >= d) ? bs[tid - d] : 0; }
        __syncthreads();
        if (tid < 256) bs[tid] = t + a;
        __syncthreads();
    }
    int off = (blockIdx.x == 0) ? 0 : bs[blockIdx.x - 1];
    int i = blockIdx.x * SCAN_T + tid;
    if (i < n) {
        int e = off + g_tmp[i];
        g_rowptr[i] = e;
        g_cursor[i] = e;
        g_deg[i] = 0;
        if (i == n - 1) g_rowptr[n] = bs[nb - 1];
    }
}

__global__ void k_scatter(const int* __restrict__ ei, int E) {
    int e = blockIdx.x * blockDim.x + threadIdx.x;
    if (e >= E) return;
    int s = ei[e];
    int d = ei[E + e];
    int p = atomicAdd(&g_cursor[d], 1);
    g_sorted_src[p] = s;
}

// ---------------- input projection (16 thr/node, float4) ---------------------
__global__ void k_inproj(const float* __restrict__ x,
                         const float* __restrict__ wsrc, const float* __restrict__ bsrc,
                         const float* __restrict__ wdst, const float* __restrict__ bdst,
                         int n) {
    int idx = blockIdx.x * blockDim.x + threadIdx.x;
    if (idx >= n * 16) return;
    int node = idx >> 4;
    int c = (idx & 15) << 2;
    const float* xr = x + (size_t)node * N_FEATS;
    float4 a = *(const float4*)(bsrc + c);
    float4 b = *(const float4*)(bdst + c);
#pragma unroll
    for (int k = 0; k < N_FEATS; k++) {
        float xv = __ldg(xr + k);
        float4 ws = *(const float4*)(wsrc + k * HID + c);
        float4 wd = *(const float4*)(wdst + k * HID + c);
        a.x += xv * ws.x; a.y += xv * ws.y; a.z += xv * ws.z; a.w += xv * ws.w;
        b.x += xv * wd.x; b.y += xv * wd.y; b.z += xv * wd.z; b.w += xv * wd.w;
    }
    *(float4*)(g_xsrc + (size_t)node * HID + c) = a;
    *(float4*)(g_xdst + (size_t)node * HID + c) = b;
}

// ---------------- softmax aggregation: warp per dst node ---------------------
__global__ void k_aggr(const float* __restrict__ fsrc,
                       const float* __restrict__ fdst,
                       float* __restrict__ y, int n) {
    int warp = (blockIdx.x * blockDim.x + threadIdx.x) >> 5;
    int lane = threadIdx.x & 31;
    if (warp >= n) return;
    int beg = g_rowptr[warp], end = g_rowptr[warp + 1];
    int c = lane * 2;
    float s0 = 0.f, s1 = 0.f, t0 = 0.f, t1 = 0.f;
    for (int base = beg; base < end; base += 32) {
        int m = end - base;
        if (m > 32) m = 32;
        int myidx = (lane < m) ? __ldg(&g_sorted_src[base + lane]) : 0;
#pragma unroll 8
        for (int j = 0; j < m; j++) {
            int src = __shfl_sync(0xffffffffu, myidx, j);
            float2 v = *(const float2*)(fsrc + (size_t)src * HID + c);
            float v0 = fmaxf(v.x, 0.f) + EPS_MSG;
            float v1 = fmaxf(v.y, 0.f) + EPS_MSG;
            float e0 = __expf(v0);
            float e1 = __expf(v1);
            s0 += e0; t0 += e0 * v0;
            s1 += e1; t1 += e1 * v1;
        }
    }
    float2 dv = *(const float2*)(fdst + (size_t)warp * HID + c);
    float2 o;
    o.x = t0 / (s0 + 1e-16f) + dv.x;
    o.y = t1 / (s1 + 1e-16f) + dv.y;
    *(float2*)(y + (size_t)warp * HID + c) = o;
}

// ---------------- GEMM1 (tf32): z = y[N,64] @ w1[64,128] + b1, fused BN stats
// One block handles full N=128 via two Bs stages reusing one As tile.
__global__ void k_gemm1_t(const float* __restrict__ y,
                          const float* __restrict__ w1, const float* __restrict__ b1,
                          float* __restrict__ z, int n) {
    __shared__ float As[64][68];
    __shared__ float Bs[64][72];
    __shared__ float ssum[HID2], ssq[HID2];
    int t = threadIdx.x;
    int row0 = blockIdx.x * 64;

    if (t < HID2) { ssum[t] = 0.f; ssq[t] = 0.f; }
    for (int i = t * 4; i < 64 * 64; i += 1024) {
        int r = i >> 6, c = i & 63;
        float4 v = make_float4(0.f, 0.f, 0.f, 0.f);
        if (row0 + r < n) v = *(const float4*)(y + (size_t)(row0 + r) * HID + c);
        float4 o;
        o.x = to_tf32(v.x); o.y = to_tf32(v.y); o.z = to_tf32(v.z); o.w = to_tf32(v.w);
        *(float4*)(&As[r][c]) = o;
    }

    int w = t >> 5, l = t & 31;
    int band = (w & 3) * 16;
    int nh = (w >> 2) * 32;
    int lq = l >> 2, lr = l & 3;
    int rA = row0 + band + lq;
    int rB = rA + 8;
    bool vA = rA < n, vB = rB < n;

    for (int s = 0; s < 2; s++) {
        int n0 = s * 64;
        if (s) __syncthreads();  // all reads of previous Bs complete
        for (int i = t * 4; i < 64 * 64; i += 1024) {
            int k = i >> 6, c = i & 63;
            float4 v = *(const float4*)(w1 + (size_t)k * HID2 + n0 + c);
            float4 o;
            o.x = to_tf32(v.x); o.y = to_tf32(v.y); o.z = to_tf32(v.z); o.w = to_tf32(v.w);
            *(float4*)(&Bs[k][c]) = o;
        }
        __syncthreads();

        float acc[4][4];
#pragma unroll
        for (int i = 0; i < 4; i++)
#pragma unroll
            for (int j = 0; j < 4; j++) acc[i][j] = 0.f;

#pragma unroll
        for (int ks = 0; ks < 8; ks++) {
            int k = ks * 8;
            float a0 = As[band + lq][k + lr];
            float a1 = As[band + lq + 8][k + lr];
            float a2 = As[band + lq][k + lr + 4];
            float a3 = As[band + lq + 8][k + lr + 4];
#pragma unroll
            for (int tj = 0; tj < 4; tj++) {
                float b0 = Bs[k + lr][nh + tj * 8 + lq];
                float bb = Bs[k + lr + 4][nh + tj * 8 + lq];
                mma_tf32(acc[tj], a0, a1, a2, a3, b0, bb);
            }
        }

#pragma unroll
        for (int tj = 0; tj < 4; tj++) {
            int colL = nh + tj * 8 + 2 * lr;
            int col = n0 + colL;
            float bx = __ldg(b1 + col), by = __ldg(b1 + col + 1);
            float oAx = acc[tj][0] + bx, oAy = acc[tj][1] + by;
            float oBx = acc[tj][2] + bx, oBy = acc[tj][3] + by;
            if (vA) { float2 o; o.x = oAx; o.y = oAy; *(float2*)(z + (size_t)rA * HID2 + col) = o; }
            if (vB) { float2 o; o.x = oBx; o.y = oBy; *(float2*)(z + (size_t)rB * HID2 + col) = o; }
            float sx = (vA ? oAx : 0.f) + (vB ? oBx : 0.f);
            float sy = (vA ? oAy : 0.f) + (vB ? oBy : 0.f);
            float qx = (vA ? oAx * oAx : 0.f) + (vB ? oBx * oBx : 0.f);
            float qy = (vA ? oAy * oAy : 0.f) + (vB ? oBy * oBy : 0.f);
#pragma unroll
            for (int off = 4; off < 32; off <<= 1) {
                sx += __shfl_xor_sync(0xffffffffu, sx, off);
                sy += __shfl_xor_sync(0xffffffffu, sy, off);
                qx += __shfl_xor_sync(0xffffffffu, qx, off);
                qy += __shfl_xor_sync(0xffffffffu, qy, off);
            }
            if (lq == 0) {
                atomicAdd(&ssum[n0 + colL], sx);
                atomicAdd(&ssum[n0 + colL + 1], sy);
                atomicAdd(&ssq[n0 + colL], qx);
                atomicAdd(&ssq[n0 + colL + 1], qy);
            }
        }
    }
    __syncthreads();
    if (t < HID2) {
        atomicAdd(&g_bnsum[t], ssum[t]);
        atomicAdd(&g_bnsq[t], ssq[t]);
    }
}

// ---------------- BN finalize (self-clearing accumulators) -------------------
__global__ void k_bnfin(const float* __restrict__ gma, const float* __restrict__ bet, float inv_n) {
    int c = threadIdx.x;
    float mu = g_bnsum[c] * inv_n;
    float var = g_bnsq[c] * inv_n - mu * mu;
    float sc = gma[c] * rsqrtf(var + BN_EPS);
    g_scale[c] = sc;
    g_shift[c] = bet[c] - mu * sc;
    g_bnsum[c] = 0.f;
    g_bnsq[c] = 0.f;
}

// ---------------- GEMM2 (tf32): h = relu( relu(BN(z)) @ w2 + b2 ) ------------
template <bool LAST>
__global__ void k_gemm2_t(const float* __restrict__ z,
                          const float* __restrict__ w2, const float* __restrict__ b2,
                          float* __restrict__ h, const int* __restrict__ bidx, int n) {
    __shared__ float As[64][68];
    __shared__ float Bs[64][72];
    int t = threadIdx.x;
    int row0 = blockIdx.x * 64;
    int w = t >> 5, l = t & 31;
    int band = (w & 3) * 16;
    int nh = (w >> 2) * 32;
    int lq = l >> 2, lr = l & 3;

    float acc[4][4];
#pragma unroll
    for (int i = 0; i < 4; i++)
#pragma unroll
        for (int j = 0; j < 4; j++) acc[i][j] = 0.f;

    for (int k0 = 0; k0 < HID2; k0 += 64) {
        __syncthreads();
        for (int i = t * 4; i < 64 * 64; i += 1024) {
            int r = i >> 6, c = i & 63;
            float4 v = make_float4(0.f, 0.f, 0.f, 0.f);
            if (row0 + r < n) v = *(const float4*)(z + (size_t)(row0 + r) * HID2 + k0 + c);
            float4 sc = *(const float4*)(&g_scale[k0 + c]);
            float4 sh = *(const float4*)(&g_shift[k0 + c]);
            float4 o;
            o.x = to_tf32(fmaxf(v.x * sc.x + sh.x, 0.f));
            o.y = to_tf32(fmaxf(v.y * sc.y + sh.y, 0.f));
            o.z = to_tf32(fmaxf(v.z * sc.z + sh.z, 0.f));
            o.w = to_tf32(fmaxf(v.w * sc.w + sh.w, 0.f));
            *(float4*)(&As[r][c]) = o;
        }
        for (int i = t * 4; i < 64 * 64; i += 1024) {
            int k = i >> 6, c = i & 63;
            float4 v = *(const float4*)(w2 + (size_t)(k0 + k) * HID + c);
            float4 o;
            o.x = to_tf32(v.x); o.y = to_tf32(v.y); o.z = to_tf32(v.z); o.w = to_tf32(v.w);
            *(float4*)(&Bs[k][c]) = o;
        }
        __syncthreads();

#pragma unroll
        for (int ks = 0; ks < 8; ks++) {
            int k = ks * 8;
            float a0 = As[band + lq][k + lr];
            float a1 = As[band + lq + 8][k + lr];
            float a2 = As[band + lq][k + lr + 4];
            float a3 = As[band + lq + 8][k + lr + 4];
#pragma unroll
            for (int tj = 0; tj < 4; tj++) {
                float b0 = Bs[k + lr][nh + tj * 8 + lq];
                float bb = Bs[k + lr + 4][nh + tj * 8 + lq];
                mma_tf32(acc[tj], a0, a1, a2, a3, b0, bb);
            }
        }
    }

    int rA = row0 + band + lq;
    int rB = rA + 8;
    bool vA = rA < n, vB = rB < n;
    int gA = 0, gB = 0;
    if (LAST) {
        if (vA) gA = __ldg(&bidx[rA]);
        if (vB) gB = __ldg(&bidx[rB]);
        if (nh == 0 && lr == 0) {
            if (vA) atomicAdd(&g_cnt[gA], 1.f);
            if (vB) atomicAdd(&g_cnt[gB], 1.f);
        }
    }
#pragma unroll
    for (int tj = 0; tj < 4; tj++) {
        int col = nh + tj * 8 + 2 * lr;
        float bx = __ldg(b2 + col), by = __ldg(b2 + col + 1);
        float oAx = fmaxf(acc[tj][0] + bx, 0.f);
        float oAy = fmaxf(acc[tj][1] + by, 0.f);
        float oBx = fmaxf(acc[tj][2] + bx, 0.f);
        float oBy = fmaxf(acc[tj][3] + by, 0.f);
        if (LAST) {
            if (vA) {
                atomicAdd(&g_pool[gA * HID + col], oAx);
                atomicAdd(&g_pool[gA * HID + col + 1], oAy);
            }
            if (vB) {
                atomicAdd(&g_pool[gB * HID + col], oBx);
                atomicAdd(&g_pool[gB * HID + col + 1], oBy);
            }
        } else {
            if (vA) { float2 o; o.x = oAx; o.y = oAy; *(float2*)(h + (size_t)rA * HID + col) = o; }
            if (vB) { float2 o; o.x = oBx; o.y = oBy; *(float2*)(h + (size_t)rB * HID + col) = o; }
        }
    }
}

// ---------------- head: warp per graph, coalesced, self-clearing --------------
__global__ void k_final(const float* __restrict__ wd, const float* __restrict__ bd,
                        float* __restrict__ out) {
    int g = (blockIdx.x * blockDim.x + threadIdx.x) >> 5;
    int lane = threadIdx.x & 31;
    if (g >= NG) return;
    float2 p = *(const float2*)(g_pool + g * HID + lane * 2);
    float w0 = __ldg(wd + lane * 2), w1v = __ldg(wd + lane * 2 + 1);
    float s = p.x * w0 + p.y * w1v;
#pragma unroll
    for (int off = 16; off > 0; off >>= 1)
        s += __shfl_xor_sync(0xffffffffu, s, off);
    if (lane == 0) {
        float icnt = 1.f / fmaxf(g_cnt[g], 1.f);
        out[g] = 1.f / (1.f + __expf(-(s * icnt + bd[0])));
        g_cnt[g] = 0.f;
    }
    float2 zz; zz.x = 0.f; zz.y = 0.f;
    *(float2*)(g_pool + g * HID + lane * 2) = zz;
}

// ---------------- host launcher -------------------------------------------------
extern "C" void kernel_launch(void* const* d_in, const int* in_sizes, int n_in,
                              void* d_out, int out_size) {
    const float* x    = (const float*)d_in[0];
    const int*   ei   = (const int*)d_in[1];
    const int*   bidx = (const int*)d_in[2];
    const float* w_src = (const float*)d_in[3];
    const float* b_src = (const float*)d_in[4];
    const float* w_dst = (const float*)d_in[5];
    const float* b_dst = (const float*)d_in[6];
    const float* w_dense = (const float*)d_in[25];
    const float* b_dense = (const float*)d_in[26];
    float* out = (float*)d_out;

    int n = in_sizes[0] / N_FEATS;
    int E = in_sizes[1] / 2;

    void *p_xsrc, *p_xdst, *p_y, *p_z, *p_h;
    cudaGetSymbolAddress(&p_xsrc, g_xsrc);
    cudaGetSymbolAddress(&p_xdst, g_xdst);
    cudaGetSymbolAddress(&p_y, g_y);
    cudaGetSymbolAddress(&p_z, g_z);
    cudaGetSymbolAddress(&p_h, g_h);

    int scan_blocks = (n + SCAN_T - 1) / SCAN_T;

    // ---- input projections (independent of CSR) ----
    k_inproj<<<(n * 16 + 255) / 256, 256>>>(x, w_src, b_src, w_dst, b_dst, n);

    // ---- CSR build (g_deg zeroed by previous call's scan_c / static init) ----
    k_hist<<<(E + 255) / 256, 256>>>(ei, E);
    k_scan_a<<<scan_blocks, SCAN_T>>>(n);
    k_scan_c<<<scan_blocks, SCAN_T>>>(n);
    k_scatter<<<(E + 255) / 256, 256>>>(ei, E);

    int aggr_blocks = (n * 32 + 255) / 256;
    int g_blocks = (n + 63) / 64;
    float inv_n = 1.f / (float)n;

    for (int layer = 0; layer < 3; layer++) {
        const float* w1 = (const float*)d_in[7 + 6 * layer + 0];
        const float* b1 = (const float*)d_in[7 + 6 * layer + 1];
        const float* gm = (const float*)d_in[7 + 6 * layer + 2];
        const float* be = (const float*)d_in[7 + 6 * layer + 3];
        const float* w2 = (const float*)d_in[7 + 6 * layer + 4];
        const float* b2 = (const float*)d_in[7 + 6 * layer + 5];

        const float* fsrc = (layer == 0) ? (const float*)p_xsrc : (const float*)p_h;
        const float* fdst = (layer == 0) ? (const float*)p_xdst : (const float*)p_h;

        k_aggr<<<aggr_blocks, 256>>>(fsrc, fdst, (float*)p_y, n);
        k_gemm1_t<<<g_blocks, 256>>>((const float*)p_y, w1, b1, (float*)p_z, n);
        k_bnfin<<<1, HID2>>>(gm, be, inv_n);
        if (layer < 2)
            k_gemm2_t<false><<<g_blocks, 256>>>((const float*)p_z, w2, b2, (float*)p_h, bidx, n);
        else
            k_gemm2_t<true><<<g_blocks, 256>>>((const float*)p_z, w2, b2, (float*)p_h, bidx, n);
    }

    k_final<<<NG / 8, 256>>>(w_dense, b_dense, out);
}